// round 16
// baseline (speedup 1.0000x reference)
#include <cuda_runtime.h>
#include <cuda_bf16.h>
#include <cstdint>

// ---------------------------------------------------------------------------
// Problem constants
// ---------------------------------------------------------------------------
namespace {
constexpr int NB = 32;       // batch
constexpr int NT = 64;       // decode steps
constexpr int NS = 128;      // source length
constexpr int EH = 512;      // encoder hidden
constexpr int DH = 512;      // decoder hidden
constexpr int NA = 256;      // attention dim
constexpr int NE = 256;      // embedding dim
constexpr int NV = 31999;    // vocab - 1
constexpr int NVP = 32000;   // padded
constexpr int IND = NE + EH; // 768
constexpr int NG = 3 * DH;   // 1536 gate rows
constexpr int NKC = 2;       // K-chunks in hh GEMM (K=256 each)
constexpr int NBLK = 128;    // persistent-loop blocks
constexpr int NM = NT * NB;  // 2048 rows of h
}

// ---------------------------------------------------------------------------
// Device scratch
// ---------------------------------------------------------------------------
__device__ __align__(16) float g_encT[NB * NA * NS];
__device__ __align__(16) float g_h[NM * DH];
__device__ __align__(16) float g_epart[NB * 4 * NS];
__device__ __align__(16) float g_gxemb[NT * NB * NG];
__device__ __align__(16) float g_gparth[NKC * NB * NG];   // hh partials [kc][b][R]
__device__ __align__(16) float g_gih[NB * NG];            // Σ_s aw_s P[b,s,:]
__device__ __align__(16) float g_P[(size_t)NB * NS * NG]; // 25 MB
// bf16 split operands
__device__ __align__(16) __nv_bfloat16 g_ahi[NM * DH];
__device__ __align__(16) __nv_bfloat16 g_alo[NM * DH];
__device__ __align__(16) __nv_bfloat16 g_bhi[(size_t)NVP * DH];
__device__ __align__(16) __nv_bfloat16 g_blo[(size_t)NVP * DH];
__device__ __align__(16) __nv_bfloat16 g_ehi[NB * NS * EH];
__device__ __align__(16) __nv_bfloat16 g_elo[NB * NS * EH];
__device__ __align__(16) __nv_bfloat16 g_pbh[NG * EH];
__device__ __align__(16) __nv_bfloat16 g_pbl[NG * EH];
__device__ __align__(16) __nv_bfloat16 g_xhi[NM * NE];    // gathered emb rows
__device__ __align__(16) __nv_bfloat16 g_xlo[NM * NE];
__device__ __align__(16) __nv_bfloat16 g_qbh[NG * NE];    // W_ih[:, :256]
__device__ __align__(16) __nv_bfloat16 g_qbl[NG * NE];

// tree barrier: 8 leaves (256B apart) + root; flip-bit per level (replay-safe)
__device__ __align__(256) unsigned int g_leaf[8 * 64];
__device__ unsigned int g_root;

// ---------------------------------------------------------------------------
// scalar helpers
// ---------------------------------------------------------------------------
__device__ __forceinline__ unsigned long long pack2(float lo, float hi) {
    unsigned long long r;
    asm("mov.b64 %0, {%1, %2};" : "=l"(r) : "f"(lo), "f"(hi));
    return r;
}
__device__ __forceinline__ void ffma2(unsigned long long& c, unsigned long long a,
                                      unsigned long long b) {
    asm("fma.rn.f32x2 %0, %1, %2, %0;" : "+l"(c) : "l"(a), "l"(b));
}
__device__ __forceinline__ void unpack2(unsigned long long v, float& lo, float& hi) {
    asm("mov.b64 {%0, %1}, %2;" : "=f"(lo), "=f"(hi) : "l"(v));
}
__device__ __forceinline__ float tanh_hw(float x) {
    float y;
    asm("tanh.approx.f32 %0, %1;" : "=f"(y) : "f"(x));
    return y;
}
__device__ __forceinline__ float fast_tanh(float x) {
    float e2 = __expf(2.0f * x);
    return 1.0f - 2.0f / (e2 + 1.0f);
}
__device__ __forceinline__ float fast_sigmoid(float x) {
    return 1.0f / (1.0f + __expf(-x));
}

// release-RMW arrival (no fence instruction -> no CCTL.IVALL)
__device__ __forceinline__ unsigned int atom_add_release(unsigned int* p,
                                                         unsigned int v) {
    unsigned int old;
    asm volatile("atom.add.release.gpu.u32 %0, [%1], %2;"
                 : "=r"(old) : "l"(p), "r"(v) : "memory");
    return old;
}
__device__ __forceinline__ unsigned int ld_relaxed(unsigned int* p) {
    unsigned int v;
    asm volatile("ld.relaxed.gpu.u32 %0, [%1];" : "=r"(v) : "l"(p) : "memory");
    return v;
}

// Tree grid barrier, fence-free (consumers use __ldcg; L2 = coherence point).
__device__ __forceinline__ void gbar(int& par) {
    __syncthreads();
    if (threadIdx.x == 0) {
        const int leaf = blockIdx.x >> 4;          // 0..7
        const bool lead = (blockIdx.x & 15) == 0;
        const unsigned int nb = lead ? (0x80000000u - 15u) : 1u;
        const unsigned int old = atom_add_release(&g_leaf[leaf * 64], nb);
        if ((((old + nb) ^ old) & 0x80000000u) != 0u) {
            const unsigned int rb = (leaf == 0) ? (0x80000000u - 7u) : 1u;
            atom_add_release(&g_root, rb);
        }
        const unsigned int want = ((unsigned int)par) << 31;
        while ((ld_relaxed(&g_root) & 0x80000000u) != want) {}
    }
    __syncthreads();
    par ^= 1;
}

__device__ __forceinline__ uint32_t smem_u32(const void* p) {
    uint32_t a;
    asm("{ .reg .u64 t; cvta.to.shared.u64 t, %1; cvt.u32.u64 %0, t; }"
        : "=r"(a) : "l"(p));
    return a;
}

// cp.async helpers
__device__ __forceinline__ void cpa16(uint32_t dst, const void* src) {
    asm volatile("cp.async.cg.shared.global [%0], [%1], 16;"
                 :: "r"(dst), "l"(src));
}
#define CPA_COMMIT() asm volatile("cp.async.commit_group;" ::: "memory")
#define CPA_WAIT0() asm volatile("cp.async.wait_group 0;" ::: "memory")

// ---------------------------------------------------------------------------
// K-pre-b: enc_projT[b][a][s]
// ---------------------------------------------------------------------------
__global__ void k_encproj(const float* __restrict__ enc,
                          const float* __restrict__ W_enc) {
    const int rs = blockIdx.x;
    const int b = rs >> 7;
    const int s = rs & 127;
    __shared__ float row[EH];
    for (int i = threadIdx.x; i < EH; i += 256) row[i] = enc[rs * EH + i];
    __syncthreads();
    const int a = threadIdx.x;
    float acc0 = 0.f, acc1 = 0.f;
#pragma unroll 8
    for (int h = 0; h < EH; h += 2) {
        acc0 += row[h] * W_enc[h * NA + a];
        acc1 += row[h + 1] * W_enc[(h + 1) * NA + a];
    }
    g_encT[(b * NA + a) * NS + s] = acc0 + acc1;
}

// ---------------------------------------------------------------------------
// bf16 split kernels
// ---------------------------------------------------------------------------
__global__ void k_split_h() {
    const int idx = (blockIdx.x * 256 + threadIdx.x) * 4;
    float4 v = *reinterpret_cast<const float4*>(&g_h[idx]);
    float x[4] = {v.x, v.y, v.z, v.w};
#pragma unroll
    for (int i = 0; i < 4; i++) {
        __nv_bfloat16 hi = __float2bfloat16(x[i]);
        g_ahi[idx + i] = hi;
        g_alo[idx + i] = __float2bfloat16(x[i] - __bfloat162float(hi));
    }
}

__global__ void k_split_enc(const float* __restrict__ enc) {
    const int idx = (blockIdx.x * 256 + threadIdx.x) * 4;
    float4 v = *reinterpret_cast<const float4*>(&enc[idx]);
    float x[4] = {v.x, v.y, v.z, v.w};
#pragma unroll
    for (int i = 0; i < 4; i++) {
        __nv_bfloat16 hi = __float2bfloat16(x[i]);
        g_ehi[idx + i] = hi;
        g_elo[idx + i] = __float2bfloat16(x[i] - __bfloat162float(hi));
    }
}

__global__ void k_split_wp(const float* __restrict__ W_ih) {
    const int idx = (blockIdx.x * 256 + threadIdx.x) * 4;  // n*512 + k
    const int n = idx >> 9;
    const int k = idx & 511;
    float4 v = *reinterpret_cast<const float4*>(&W_ih[(size_t)n * IND + NE + k]);
    float x[4] = {v.x, v.y, v.z, v.w};
#pragma unroll
    for (int i = 0; i < 4; i++) {
        __nv_bfloat16 hi = __float2bfloat16(x[i]);
        g_pbh[idx + i] = hi;
        g_pbl[idx + i] = __float2bfloat16(x[i] - __bfloat162float(hi));
    }
}

// W_ih[:, 0:256] rows -> g_qbh/g_qbl [1536][256]
__global__ void k_split_wq(const float* __restrict__ W_ih) {
    const int idx = (blockIdx.x * 256 + threadIdx.x) * 4;  // n*256 + k
    const int n = idx >> 8;
    const int k = idx & 255;
    float4 v = *reinterpret_cast<const float4*>(&W_ih[(size_t)n * IND + k]);
    float x[4] = {v.x, v.y, v.z, v.w};
#pragma unroll
    for (int i = 0; i < 4; i++) {
        __nv_bfloat16 hi = __float2bfloat16(x[i]);
        g_qbh[idx + i] = hi;
        g_qbl[idx + i] = __float2bfloat16(x[i] - __bfloat162float(hi));
    }
}

// gather emb rows: g_xhi/g_xlo[m][k], m = t*NB + b, tok = y[b][t]
__global__ void k_gather_emb(const int* __restrict__ y,
                             const float* __restrict__ embedding) {
    const int idx = (blockIdx.x * 256 + threadIdx.x) * 4;  // m*256 + k
    const int m = idx >> 8;
    const int k = idx & 255;
    const int tok = y[(m & 31) * NT + (m >> 5)];
    float4 v = *reinterpret_cast<const float4*>(&embedding[(size_t)tok * NE + k]);
    float x[4] = {v.x, v.y, v.z, v.w};
#pragma unroll
    for (int i = 0; i < 4; i++) {
        __nv_bfloat16 hi = __float2bfloat16(x[i]);
        g_xhi[idx + i] = hi;
        g_xlo[idx + i] = __float2bfloat16(x[i] - __bfloat162float(hi));
    }
}

__global__ void k_split_w(const float* __restrict__ Wfc) {
    __shared__ float tile[32][33];
    const int n0 = blockIdx.x * 32;
    const int k0 = blockIdx.y * 32;
    const int tx = threadIdx.x & 31;
    const int ty0 = threadIdx.x >> 5;
#pragma unroll
    for (int i = 0; i < 32; i += 8) {
        const int n = n0 + tx;
        tile[ty0 + i][tx] =
            (n < NV) ? Wfc[(size_t)(k0 + ty0 + i) * NV + n] : 0.f;
    }
    __syncthreads();
#pragma unroll
    for (int i = 0; i < 32; i += 8) {
        const int n = n0 + ty0 + i;
        const float w = tile[tx][ty0 + i];
        __nv_bfloat16 hi = __float2bfloat16(w);
        g_bhi[(size_t)n * DH + k0 + tx] = hi;
        g_blo[(size_t)n * DH + k0 + tx] =
            __float2bfloat16(w - __bfloat162float(hi));
    }
}

// ---------------------------------------------------------------------------
// mma.sync helpers
// ---------------------------------------------------------------------------
__device__ __forceinline__ void ldsm_x4(uint32_t& r0, uint32_t& r1,
                                        uint32_t& r2, uint32_t& r3,
                                        uint32_t addr) {
    asm volatile(
        "ldmatrix.sync.aligned.m8n8.x4.shared.b16 {%0,%1,%2,%3}, [%4];"
        : "=r"(r0), "=r"(r1), "=r"(r2), "=r"(r3) : "r"(addr));
}
__device__ __forceinline__ void ldsm_x2(uint32_t& r0, uint32_t& r1,
                                        uint32_t addr) {
    asm volatile(
        "ldmatrix.sync.aligned.m8n8.x2.shared.b16 {%0,%1}, [%2];"
        : "=r"(r0), "=r"(r1) : "r"(addr));
}
__device__ __forceinline__ void mma_bf16(float* c, const uint32_t* a,
                                         const uint32_t* b) {
    asm volatile(
        "mma.sync.aligned.m16n8k16.row.col.f32.bf16.bf16.f32 "
        "{%0,%1,%2,%3}, {%4,%5,%6,%7}, {%8,%9}, {%0,%1,%2,%3};"
        : "+f"(c[0]), "+f"(c[1]), "+f"(c[2]), "+f"(c[3])
        : "r"(a[0]), "r"(a[1]), "r"(a[2]), "r"(a[3]), "r"(b[0]), "r"(b[1]));
}

// Double-buffered cp.async HMMA 3-term split GEMM (dynamic smem, 80 KB).
constexpr int ROWB = 80;          // bytes per smem row
constexpr int ARRB = 128 * ROWB;  // 10240 bytes per array
constexpr int BUFB = 4 * ARRB;    // 40960 bytes per buffer
constexpr int HMMA_SMEM = 2 * BUFB;

// KDIM = K extent of A/B rows; NCH = KDIM/32 chunks; OSTR = out row stride
template <bool FC_OUT, int KDIM>
__device__ __forceinline__ void hmma_tile(
        const __nv_bfloat16* __restrict__ Ahi, const __nv_bfloat16* __restrict__ Alo,
        const __nv_bfloat16* __restrict__ Bhi, const __nv_bfloat16* __restrict__ Blo,
        int m0, int n0, const float* __restrict__ bfc, float* __restrict__ out) {
    constexpr int NCH = KDIM / 32;
    extern __shared__ __align__(16) char smem[];
    const uint32_t sb = smem_u32(smem);

    const int tid = threadIdx.x;
    const int wid = tid >> 5;
    const int lane = tid & 31;
    const int wm = wid & 1;
    const int wn = wid >> 1;

    float acc[4][4][4];
#pragma unroll
    for (int i = 0; i < 4; i++)
#pragma unroll
        for (int j = 0; j < 4; j++)
#pragma unroll
            for (int q = 0; q < 4; q++) acc[i][j][q] = 0.f;

    const int a_row = wm * 64 + (lane & 15);
    const int a_cb = (lane >> 4) * 16;
    const int b_row = wn * 32 + (lane & 7);
    const int b_cb = ((lane >> 3) & 1) * 16;
    const int g_r0 = tid >> 2;
    const int g_c0 = (tid & 3) * 8;

#pragma unroll
    for (int i = 0; i < 2; i++) {
        const int row = g_r0 + i * 64;
        const size_t ga = (size_t)(m0 + row) * KDIM + g_c0;
        const size_t gb = (size_t)(n0 + row) * KDIM + g_c0;
        const uint32_t so = row * ROWB + g_c0 * 2;
        cpa16(sb + 0 * ARRB + so, Ahi + ga);
        cpa16(sb + 1 * ARRB + so, Alo + ga);
        cpa16(sb + 2 * ARRB + so, Bhi + gb);
        cpa16(sb + 3 * ARRB + so, Blo + gb);
    }
    CPA_COMMIT();

    for (int c = 0; c < NCH; c++) {
        const uint32_t cur = sb + (c & 1) * BUFB;
        CPA_WAIT0();
        __syncthreads();
        if (c < NCH - 1) {
            const uint32_t nxt = sb + ((c + 1) & 1) * BUFB;
            const int kg = (c + 1) * 32;
#pragma unroll
            for (int i = 0; i < 2; i++) {
                const int row = g_r0 + i * 64;
                const size_t ga = (size_t)(m0 + row) * KDIM + kg + g_c0;
                const size_t gb = (size_t)(n0 + row) * KDIM + kg + g_c0;
                const uint32_t so = row * ROWB + g_c0 * 2;
                cpa16(nxt + 0 * ARRB + so, Ahi + ga);
                cpa16(nxt + 1 * ARRB + so, Alo + ga);
                cpa16(nxt + 2 * ARRB + so, Bhi + gb);
                cpa16(nxt + 3 * ARRB + so, Blo + gb);
            }
            CPA_COMMIT();
        }

#pragma unroll
        for (int ks = 0; ks < 2; ks++) {
            const int kb = ks * 32;
            uint32_t ah[4][4], al[4][4], bh[4][2], bl[4][2];
#pragma unroll
            for (int mt = 0; mt < 4; mt++) {
                const uint32_t ro = (a_row + mt * 16) * ROWB + kb + a_cb;
                ldsm_x4(ah[mt][0], ah[mt][1], ah[mt][2], ah[mt][3],
                        cur + 0 * ARRB + ro);
                ldsm_x4(al[mt][0], al[mt][1], al[mt][2], al[mt][3],
                        cur + 1 * ARRB + ro);
            }
#pragma unroll
            for (int nt = 0; nt < 4; nt++) {
                const uint32_t ro = (b_row + nt * 8) * ROWB + kb + b_cb;
                ldsm_x2(bh[nt][0], bh[nt][1], cur + 2 * ARRB + ro);
                ldsm_x2(bl[nt][0], bl[nt][1], cur + 3 * ARRB + ro);
            }
#pragma unroll
            for (int mt = 0; mt < 4; mt++)
#pragma unroll
                for (int nt = 0; nt < 4; nt++) {
                    mma_bf16(acc[mt][nt], ah[mt], bh[nt]);
                    mma_bf16(acc[mt][nt], ah[mt], bl[nt]);
                    mma_bf16(acc[mt][nt], al[mt], bh[nt]);
                }
        }
    }

#pragma unroll
    for (int mt = 0; mt < 4; mt++) {
#pragma unroll
        for (int half = 0; half < 2; half++) {
            const int m = m0 + wm * 64 + mt * 16 + (lane >> 2) + half * 8;
            float* orow;
            if (FC_OUT) {
                const int tt = m >> 5, bb = m & 31;
                orow = out + ((size_t)(bb * NT + tt)) * NV;
            } else {
                orow = out + (size_t)m * NG;
            }
#pragma unroll
            for (int nt = 0; nt < 4; nt++) {
                const int n = n0 + wn * 32 + nt * 8 + (lane & 3) * 2;
                const float v0 = acc[mt][nt][half * 2 + 0];
                const float v1 = acc[mt][nt][half * 2 + 1];
                if (FC_OUT) {
                    if (n < NV) orow[n] = v0 + bfc[n];
                    if (n + 1 < NV) orow[n + 1] = v1 + bfc[n + 1];
                } else {
                    orow[n] = v0;
                    orow[n + 1] = v1;
                }
            }
        }
    }
}

__global__ void __launch_bounds__(256) k_fc_mma(const float* __restrict__ bfc,
                                                float* __restrict__ out) {
    hmma_tile<true, DH>(g_ahi, g_alo, g_bhi, g_blo,
                        blockIdx.y * 128, blockIdx.x * 128, bfc, out);
}

__global__ void __launch_bounds__(256) k_pgemm() {
    hmma_tile<false, DH>(g_ehi, g_elo, g_pbh, g_pbl,
                         blockIdx.y * 128, blockIdx.x * 128, nullptr, g_P);
}

// gx_emb[m][n] = emb_m . W_ih[n][:256]   (m = t*NB+b)
__global__ void __launch_bounds__(256) k_gxemb_mma() {
    hmma_tile<false, NE>(g_xhi, g_xlo, g_qbh, g_qbl,
                         blockIdx.y * 128, blockIdx.x * 128, nullptr, g_gxemb);
}

// ---------------------------------------------------------------------------
// K-loop: persistent, 512 thr x 128 blocks, TWO phases per step.
//  A: combine h_{t-1} + energy partials
//  B: blocks 0-47: W_hh GEMM (kc=2, K=256); blocks 48-111: softmax + gih half
// ---------------------------------------------------------------------------
struct SA {
    float dpart[8][64];
    float decs[64];
    float vsh[64];
    float ep[4][NS];
};
struct SB {
    float aw[NS];
};
struct SG {
    float As[32][64];
    float Bs[32][36];
};
union SmemU {
    SA a;
    SB b;
    SG g;
};

__device__ __forceinline__ void gate_gemm_hh(
        const float* __restrict__ W_hh, int wr0,
        const float* __restrict__ bsrc, int kc, SG& sg, int tid) {
    const int p0 = tid >> 4;
    const int bg = (tid & 15) * 2;
    unsigned long long acc0 = 0ull, acc1 = 0ull;

    const int arow = tid & 63;
    const int akq = (tid >> 6) * 4;
    const int bb = tid >> 4;
    const int bk2 = (tid & 15) * 2;
    const float* wrow = W_hh + (size_t)(wr0 + arow) * DH;

#pragma unroll
    for (int kt = 0; kt < 8; kt++) {
        const int kg0 = kc * 256 + kt * 32;
        float4 a4 = *reinterpret_cast<const float4*>(wrow + kg0 + akq);
        sg.As[akq + 0][arow] = a4.x;
        sg.As[akq + 1][arow] = a4.y;
        sg.As[akq + 2][arow] = a4.z;
        sg.As[akq + 3][arow] = a4.w;
        float2 b2 = __ldcg(reinterpret_cast<const float2*>(
            bsrc + bb * 512 + kg0 + bk2));
        sg.Bs[bk2 + 0][bb] = b2.x;
        sg.Bs[bk2 + 1][bb] = b2.y;
        __syncthreads();
#pragma unroll
        for (int kk = 0; kk < 32; kk++) {
            float2 av = *reinterpret_cast<const float2*>(&sg.As[kk][2 * p0]);
            unsigned long long a2 = pack2(av.x, av.y);
            float b0 = sg.Bs[kk][bg];
            float b1 = sg.Bs[kk][bg + 1];
            ffma2(acc0, a2, pack2(b0, b0));
            ffma2(acc1, a2, pack2(b1, b1));
        }
        __syncthreads();
    }
    const int r = wr0 + 2 * p0;
    float lo, hi;
    unpack2(acc0, lo, hi);
    *reinterpret_cast<float2*>(
        &g_gparth[((size_t)(kc * NB + bg)) * NG + r]) = make_float2(lo, hi);
    unpack2(acc1, lo, hi);
    *reinterpret_cast<float2*>(
        &g_gparth[((size_t)(kc * NB + bg + 1)) * NG + r]) = make_float2(lo, hi);
}

__global__ void __launch_bounds__(512) k_loop(
        const float* __restrict__ dec_init,
        const int* __restrict__ mask,
        const float* __restrict__ W_dec,
        const float* __restrict__ v,
        const float* __restrict__ W_hh,
        const float* __restrict__ b_ih,
        const float* __restrict__ b_hh,
        float* __restrict__ attn_out) {
    const int blk = blockIdx.x;
    const int tid = threadIdx.x;
    __shared__ SmemU sm;
    __shared__ __align__(16) float s_prev[DH];

    const int ab = blk >> 2;   // batch element (phase A)
    const int at = blk & 3;    // a-tile quadrant

    int par = (int)(ld_relaxed(&g_root) >> 31) ^ 1;

    for (int t = 0; t <= NT; t++) {
        // ---------------- Phase A: combine h_{t-1}, then energy
        if (t == 0) {
            s_prev[tid] = dec_init[ab * DH + tid];
        } else {
            const int i = tid;
            float gx[3], gh[3];
#pragma unroll
            for (int g = 0; g < 3; g++) {
                const int R = g * DH + i;
                gx[g] = __ldcg(&g_gxemb[((size_t)(t - 1) * NB + ab) * NG + R]) +
                        __ldcg(&g_gih[ab * NG + R]) + b_ih[R];
                gh[g] = __ldcg(&g_gparth[(size_t)ab * NG + R]) +
                        __ldcg(&g_gparth[((size_t)(NB + ab)) * NG + R]) +
                        b_hh[R];
            }
            const float r = fast_sigmoid(gx[0] + gh[0]);
            const float z = fast_sigmoid(gx[1] + gh[1]);
            const float n = fast_tanh(gx[2] + r * gh[2]);
            const float hn = (1.0f - z) * n + z * s_prev[i];
            s_prev[i] = hn;
            if (at == 0) g_h[((size_t)(t - 1) * NB + ab) * DH + i] = hn;
        }
        if (t == NT) break;

        {
            const int a0 = at * 64;
            if (tid < 64) sm.a.vsh[tid] = v[a0 + tid];
            __syncthreads();

            {
                const int j = tid & 63;
                const int hq = tid >> 6;
                const float* W0 = W_dec + (size_t)(hq * 64) * NA + a0 + j;
                const float* pr = s_prev + hq * 64;
                float c[8];
#pragma unroll
                for (int u = 0; u < 8; u++) c[u] = 0.f;
#pragma unroll
                for (int h = 0; h < 64; h += 8) {
#pragma unroll
                    for (int u = 0; u < 8; u++)
                        c[u] += pr[h + u] * W0[(h + u) * NA];
                }
                float s0 = 0.f;
#pragma unroll
                for (int u = 0; u < 8; u++) s0 += c[u];
                sm.a.dpart[hq][j] = s0;
            }
            __syncthreads();
            if (tid < 64) {
                float s0 = 0.f;
#pragma unroll
                for (int q = 0; q < 8; q++) s0 += sm.a.dpart[q][tid];
                sm.a.decs[tid] = s0;
            }
            __syncthreads();

            {
                const int ah = tid >> 7;
                const int ss = tid & 127;
                const float* et =
                    g_encT + ((size_t)ab * NA + a0 + ah * 16) * NS + ss;
                const float* dv = sm.a.decs + ah * 16;
                const float* vv = sm.a.vsh + ah * 16;
                float c[4];
#pragma unroll
                for (int u = 0; u < 4; u++) c[u] = 0.f;
#pragma unroll
                for (int a = 0; a < 16; a += 4) {
#pragma unroll
                    for (int u = 0; u < 4; u++)
                        c[u] += tanh_hw(et[(a + u) * NS] + dv[a + u]) * vv[a + u];
                }
                sm.a.ep[ah][ss] = (c[0] + c[1]) + (c[2] + c[3]);
            }
            __syncthreads();
            if (tid < NS)
                g_epart[((size_t)ab * 4 + at) * NS + tid] =
                    (sm.a.ep[0][tid] + sm.a.ep[1][tid]) +
                    (sm.a.ep[2][tid] + sm.a.ep[3][tid]);
        }
        gbar(par);

        // ---------------- Phase B
        if (blk < 48) {
            // hh GEMM: mt = blk>>1 (64-row tile), kc = blk&1 (K=256)
            const float* bsrc = (t == 0) ? dec_init
                                         : (g_h + (size_t)(t - 1) * NB * DH);
            gate_gemm_hh(W_hh, (blk >> 1) * 64, bsrc, blk & 1, sm.g, tid);
        } else if (blk < 112) {
            const int idx = blk - 48;
            const int b = idx >> 1;
            const int rhalf = idx & 1;
            if (tid < 32) {
                float en[4];
#pragma unroll
                for (int j = 0; j < 4; j++) {
                    const int s = tid + j * 32;
                    const float* gp = g_epart + (size_t)(b * 4) * NS + s;
                    float x = (__ldcg(gp) + __ldcg(gp + NS)) +
                              (__ldcg(gp + 2 * NS) + __ldcg(gp + 3 * NS));
                    if (mask[b * NS + s] == 0) x = -1e9f;
                    en[j] = x;
                }
                float mx = fmaxf(fmaxf(en[0], en[1]), fmaxf(en[2], en[3]));
#pragma unroll
                for (int off = 16; off > 0; off >>= 1)
                    mx = fmaxf(mx, __shfl_xor_sync(0xffffffffu, mx, off));
                float sum = 0.f;
#pragma unroll
                for (int j = 0; j < 4; j++) {
                    en[j] = __expf(en[j] - mx);
                    sum += en[j];
                }
#pragma unroll
                for (int off = 16; off > 0; off >>= 1)
                    sum += __shfl_xor_sync(0xffffffffu, sum, off);
                const float inv = 1.0f / sum;
#pragma unroll
                for (int j = 0; j < 4; j++) {
                    const float w = en[j] * inv;
                    sm.b.aw[tid + j * 32] = w;
                    if (rhalf == 0)
                        attn_out[((size_t)(b * NT + t)) * NS + tid + j * 32] = w;
                }
            }
            __syncthreads();
            // gih half: 192 threads x float4 rows, 8-deep s-MLP
            if (tid < 192) {
                const int R = rhalf * 768 + tid * 4;
                const float* pb = g_P + ((size_t)b * NS) * NG + R;
                float4 c[4];
#pragma unroll
                for (int q = 0; q < 4; q++) c[q] = make_float4(0.f, 0.f, 0.f, 0.f);
#pragma unroll 4
                for (int s = 0; s < NS; s += 4) {
#pragma unroll
                    for (int q = 0; q < 4; q++) {
                        float4 vv = __ldcg(reinterpret_cast<const float4*>(
                            pb + (size_t)(s + q) * NG));
                        const float w = sm.b.aw[s + q];
                        c[q].x += w * vv.x;
                        c[q].y += w * vv.y;
                        c[q].z += w * vv.z;
                        c[q].w += w * vv.w;
                    }
                }
                float4 o;
                o.x = (c[0].x + c[1].x) + (c[2].x + c[3].x);
                o.y = (c[0].y + c[1].y) + (c[2].y + c[3].y);
                o.z = (c[0].z + c[1].z) + (c[2].z + c[3].z);
                o.w = (c[0].w + c[1].w) + (c[2].w + c[3].w);
                *reinterpret_cast<float4*>(&g_gih[b * NG + R]) = o;
            }
        }
        gbar(par);
    }
}

// ---------------------------------------------------------------------------
// Launch
// ---------------------------------------------------------------------------
extern "C" void kernel_launch(void* const* d_in, const int* in_sizes, int n_in,
                              void* d_out, int out_size) {
    const int* y = (const int*)d_in[0];
    const float* enc = (const float*)d_in[1];
    const float* dec_init = (const float*)d_in[2];
    const int* mask = (const int*)d_in[3];
    const float* emb = (const float*)d_in[4];
    const float* W_enc = (const float*)d_in[5];
    const float* W_dec = (const float*)d_in[6];
    const float* v = (const float*)d_in[7];
    const float* W_ih = (const float*)d_in[8];
    const float* W_hh = (const float*)d_in[9];
    const float* b_ih = (const float*)d_in[10];
    const float* b_hh = (const float*)d_in[11];
    const float* W_fc = (const float*)d_in[12];
    const float* b_fc = (const float*)d_in[13];

    float* out = (float*)d_out;
    float* attn_out = out + (size_t)NB * NT * NV;

    cudaFuncSetAttribute(k_fc_mma, cudaFuncAttributeMaxDynamicSharedMemorySize,
                         HMMA_SMEM);
    cudaFuncSetAttribute(k_pgemm, cudaFuncAttributeMaxDynamicSharedMemorySize,
                         HMMA_SMEM);
    cudaFuncSetAttribute(k_gxemb_mma,
                         cudaFuncAttributeMaxDynamicSharedMemorySize, HMMA_SMEM);

    k_encproj<<<NB * NS, 256>>>(enc, W_enc);
    k_gather_emb<<<(NM * NE) / (256 * 4), 256>>>(y, emb);
    k_split_wq<<<(NG * NE) / (256 * 4), 256>>>(W_ih);
    k_split_w<<<dim3(NVP / 32, DH / 32), 256>>>(W_fc);
    k_split_enc<<<(NB * NS * EH) / (256 * 4), 256>>>(enc);
    k_split_wp<<<(NG * EH) / (256 * 4), 256>>>(W_ih);
    k_gxemb_mma<<<dim3(NG / 128, NM / 128), 256, HMMA_SMEM>>>();
    k_pgemm<<<dim3(NG / 128, (NB * NS) / 128), 256, HMMA_SMEM>>>();
    k_loop<<<NBLK, 512>>>(dec_init, mask, W_dec, v, W_hh, b_ih, b_hh, attn_out);
    k_split_h<<<(NM * DH) / (256 * 4), 256>>>();
    k_fc_mma<<<dim3(NVP / 128, NM / 128), 256, HMMA_SMEM>>>(b_fc, out);
}

// round 17
// speedup vs baseline: 1.0524x; 1.0524x over previous
#include <cuda_runtime.h>
#include <cuda_bf16.h>
#include <cstdint>

// ---------------------------------------------------------------------------
// Problem constants
// ---------------------------------------------------------------------------
namespace {
constexpr int NB = 32;       // batch
constexpr int NT = 64;       // decode steps
constexpr int NS = 128;      // source length
constexpr int EH = 512;      // encoder hidden
constexpr int DH = 512;      // decoder hidden
constexpr int NA = 256;      // attention dim
constexpr int NE = 256;      // embedding dim
constexpr int NV = 31999;    // vocab - 1
constexpr int NVP = 32000;   // padded
constexpr int IND = NE + EH; // 768
constexpr int NG = 3 * DH;   // 1536 gate rows
constexpr int NKC = 4;       // K-chunks in hh GEMM (K=128 each)  [r15 value]
constexpr int NBLK = 128;    // persistent-loop blocks
constexpr int NM = NT * NB;  // 2048 rows of h
}

// ---------------------------------------------------------------------------
// Device scratch
// ---------------------------------------------------------------------------
__device__ __align__(16) float g_encT[NB * NA * NS];
__device__ __align__(16) float g_h[NM * DH];
__device__ __align__(16) float g_epart[NB * 4 * NS];
__device__ __align__(16) float g_gxemb[NT * NB * NG];
__device__ __align__(16) float g_gparth[NKC * NB * NG];   // hh partials [kc][b][R]
__device__ __align__(16) float g_gih[NB * NG];            // Σ_s aw_s P[b,s,:]
__device__ __align__(16) float g_P[(size_t)NB * NS * NG]; // 25 MB
// bf16 split operands
__device__ __align__(16) __nv_bfloat16 g_ahi[NM * DH];
__device__ __align__(16) __nv_bfloat16 g_alo[NM * DH];
__device__ __align__(16) __nv_bfloat16 g_bhi[(size_t)NVP * DH];
__device__ __align__(16) __nv_bfloat16 g_blo[(size_t)NVP * DH];
__device__ __align__(16) __nv_bfloat16 g_ehi[NB * NS * EH];
__device__ __align__(16) __nv_bfloat16 g_elo[NB * NS * EH];
__device__ __align__(16) __nv_bfloat16 g_pbh[NG * EH];
__device__ __align__(16) __nv_bfloat16 g_pbl[NG * EH];
__device__ __align__(16) __nv_bfloat16 g_xhi[NM * NE];    // gathered emb rows
__device__ __align__(16) __nv_bfloat16 g_xlo[NM * NE];
__device__ __align__(16) __nv_bfloat16 g_qbh[NG * NE];    // W_ih[:, :256]
__device__ __align__(16) __nv_bfloat16 g_qbl[NG * NE];

// tree barrier: 8 leaves (256B apart) + root; flip-bit per level (replay-safe)
__device__ __align__(256) unsigned int g_leaf[8 * 64];
__device__ unsigned int g_root;

// ---------------------------------------------------------------------------
// scalar helpers
// ---------------------------------------------------------------------------
__device__ __forceinline__ unsigned long long pack2(float lo, float hi) {
    unsigned long long r;
    asm("mov.b64 %0, {%1, %2};" : "=l"(r) : "f"(lo), "f"(hi));
    return r;
}
__device__ __forceinline__ void ffma2(unsigned long long& c, unsigned long long a,
                                      unsigned long long b) {
    asm("fma.rn.f32x2 %0, %1, %2, %0;" : "+l"(c) : "l"(a), "l"(b));
}
__device__ __forceinline__ void unpack2(unsigned long long v, float& lo, float& hi) {
    asm("mov.b64 {%0, %1}, %2;" : "=f"(lo), "=f"(hi) : "l"(v));
}
__device__ __forceinline__ float tanh_hw(float x) {
    float y;
    asm("tanh.approx.f32 %0, %1;" : "=f"(y) : "f"(x));
    return y;
}
__device__ __forceinline__ float fast_tanh(float x) {
    float e2 = __expf(2.0f * x);
    return 1.0f - 2.0f / (e2 + 1.0f);
}
__device__ __forceinline__ float fast_sigmoid(float x) {
    return 1.0f / (1.0f + __expf(-x));
}

// release-RMW arrival (no fence instruction -> no CCTL.IVALL)
__device__ __forceinline__ unsigned int atom_add_release(unsigned int* p,
                                                         unsigned int v) {
    unsigned int old;
    asm volatile("atom.add.release.gpu.u32 %0, [%1], %2;"
                 : "=r"(old) : "l"(p), "r"(v) : "memory");
    return old;
}
__device__ __forceinline__ unsigned int ld_relaxed(unsigned int* p) {
    unsigned int v;
    asm volatile("ld.relaxed.gpu.u32 %0, [%1];" : "=r"(v) : "l"(p) : "memory");
    return v;
}

// Tree grid barrier, fence-free (consumers use __ldcg; L2 = coherence point).
__device__ __forceinline__ void gbar(int& par) {
    __syncthreads();
    if (threadIdx.x == 0) {
        const int leaf = blockIdx.x >> 4;          // 0..7
        const bool lead = (blockIdx.x & 15) == 0;
        const unsigned int nb = lead ? (0x80000000u - 15u) : 1u;
        const unsigned int old = atom_add_release(&g_leaf[leaf * 64], nb);
        if ((((old + nb) ^ old) & 0x80000000u) != 0u) {
            const unsigned int rb = (leaf == 0) ? (0x80000000u - 7u) : 1u;
            atom_add_release(&g_root, rb);
        }
        const unsigned int want = ((unsigned int)par) << 31;
        while ((ld_relaxed(&g_root) & 0x80000000u) != want) {}
    }
    __syncthreads();
    par ^= 1;
}

__device__ __forceinline__ uint32_t smem_u32(const void* p) {
    uint32_t a;
    asm("{ .reg .u64 t; cvta.to.shared.u64 t, %1; cvt.u32.u64 %0, t; }"
        : "=r"(a) : "l"(p));
    return a;
}

// cp.async helpers
__device__ __forceinline__ void cpa16(uint32_t dst, const void* src) {
    asm volatile("cp.async.cg.shared.global [%0], [%1], 16;"
                 :: "r"(dst), "l"(src));
}
#define CPA_COMMIT() asm volatile("cp.async.commit_group;" ::: "memory")
#define CPA_WAIT0() asm volatile("cp.async.wait_group 0;" ::: "memory")

// ---------------------------------------------------------------------------
// K-pre-b: enc_projT[b][a][s]
// ---------------------------------------------------------------------------
__global__ void k_encproj(const float* __restrict__ enc,
                          const float* __restrict__ W_enc) {
    const int rs = blockIdx.x;
    const int b = rs >> 7;
    const int s = rs & 127;
    __shared__ float row[EH];
    for (int i = threadIdx.x; i < EH; i += 256) row[i] = enc[rs * EH + i];
    __syncthreads();
    const int a = threadIdx.x;
    float acc0 = 0.f, acc1 = 0.f;
#pragma unroll 8
    for (int h = 0; h < EH; h += 2) {
        acc0 += row[h] * W_enc[h * NA + a];
        acc1 += row[h + 1] * W_enc[(h + 1) * NA + a];
    }
    g_encT[(b * NA + a) * NS + s] = acc0 + acc1;
}

// ---------------------------------------------------------------------------
// bf16 split kernels
// ---------------------------------------------------------------------------
__global__ void k_split_h() {
    const int idx = (blockIdx.x * 256 + threadIdx.x) * 4;
    float4 v = *reinterpret_cast<const float4*>(&g_h[idx]);
    float x[4] = {v.x, v.y, v.z, v.w};
#pragma unroll
    for (int i = 0; i < 4; i++) {
        __nv_bfloat16 hi = __float2bfloat16(x[i]);
        g_ahi[idx + i] = hi;
        g_alo[idx + i] = __float2bfloat16(x[i] - __bfloat162float(hi));
    }
}

__global__ void k_split_enc(const float* __restrict__ enc) {
    const int idx = (blockIdx.x * 256 + threadIdx.x) * 4;
    float4 v = *reinterpret_cast<const float4*>(&enc[idx]);
    float x[4] = {v.x, v.y, v.z, v.w};
#pragma unroll
    for (int i = 0; i < 4; i++) {
        __nv_bfloat16 hi = __float2bfloat16(x[i]);
        g_ehi[idx + i] = hi;
        g_elo[idx + i] = __float2bfloat16(x[i] - __bfloat162float(hi));
    }
}

__global__ void k_split_wp(const float* __restrict__ W_ih) {
    const int idx = (blockIdx.x * 256 + threadIdx.x) * 4;  // n*512 + k
    const int n = idx >> 9;
    const int k = idx & 511;
    float4 v = *reinterpret_cast<const float4*>(&W_ih[(size_t)n * IND + NE + k]);
    float x[4] = {v.x, v.y, v.z, v.w};
#pragma unroll
    for (int i = 0; i < 4; i++) {
        __nv_bfloat16 hi = __float2bfloat16(x[i]);
        g_pbh[idx + i] = hi;
        g_pbl[idx + i] = __float2bfloat16(x[i] - __bfloat162float(hi));
    }
}

// W_ih[:, 0:256] rows -> g_qbh/g_qbl [1536][256]
__global__ void k_split_wq(const float* __restrict__ W_ih) {
    const int idx = (blockIdx.x * 256 + threadIdx.x) * 4;  // n*256 + k
    const int n = idx >> 8;
    const int k = idx & 255;
    float4 v = *reinterpret_cast<const float4*>(&W_ih[(size_t)n * IND + k]);
    float x[4] = {v.x, v.y, v.z, v.w};
#pragma unroll
    for (int i = 0; i < 4; i++) {
        __nv_bfloat16 hi = __float2bfloat16(x[i]);
        g_qbh[idx + i] = hi;
        g_qbl[idx + i] = __float2bfloat16(x[i] - __bfloat162float(hi));
    }
}

// gather emb rows: g_xhi/g_xlo[m][k], m = t*NB + b, tok = y[b][t]
__global__ void k_gather_emb(const int* __restrict__ y,
                             const float* __restrict__ embedding) {
    const int idx = (blockIdx.x * 256 + threadIdx.x) * 4;  // m*256 + k
    const int m = idx >> 8;
    const int k = idx & 255;
    const int tok = y[(m & 31) * NT + (m >> 5)];
    float4 v = *reinterpret_cast<const float4*>(&embedding[(size_t)tok * NE + k]);
    float x[4] = {v.x, v.y, v.z, v.w};
#pragma unroll
    for (int i = 0; i < 4; i++) {
        __nv_bfloat16 hi = __float2bfloat16(x[i]);
        g_xhi[idx + i] = hi;
        g_xlo[idx + i] = __float2bfloat16(x[i] - __bfloat162float(hi));
    }
}

__global__ void k_split_w(const float* __restrict__ Wfc) {
    __shared__ float tile[32][33];
    const int n0 = blockIdx.x * 32;
    const int k0 = blockIdx.y * 32;
    const int tx = threadIdx.x & 31;
    const int ty0 = threadIdx.x >> 5;
#pragma unroll
    for (int i = 0; i < 32; i += 8) {
        const int n = n0 + tx;
        tile[ty0 + i][tx] =
            (n < NV) ? Wfc[(size_t)(k0 + ty0 + i) * NV + n] : 0.f;
    }
    __syncthreads();
#pragma unroll
    for (int i = 0; i < 32; i += 8) {
        const int n = n0 + ty0 + i;
        const float w = tile[tx][ty0 + i];
        __nv_bfloat16 hi = __float2bfloat16(w);
        g_bhi[(size_t)n * DH + k0 + tx] = hi;
        g_blo[(size_t)n * DH + k0 + tx] =
            __float2bfloat16(w - __bfloat162float(hi));
    }
}

// ---------------------------------------------------------------------------
// mma.sync helpers
// ---------------------------------------------------------------------------
__device__ __forceinline__ void ldsm_x4(uint32_t& r0, uint32_t& r1,
                                        uint32_t& r2, uint32_t& r3,
                                        uint32_t addr) {
    asm volatile(
        "ldmatrix.sync.aligned.m8n8.x4.shared.b16 {%0,%1,%2,%3}, [%4];"
        : "=r"(r0), "=r"(r1), "=r"(r2), "=r"(r3) : "r"(addr));
}
__device__ __forceinline__ void ldsm_x2(uint32_t& r0, uint32_t& r1,
                                        uint32_t addr) {
    asm volatile(
        "ldmatrix.sync.aligned.m8n8.x2.shared.b16 {%0,%1}, [%2];"
        : "=r"(r0), "=r"(r1) : "r"(addr));
}
__device__ __forceinline__ void mma_bf16(float* c, const uint32_t* a,
                                         const uint32_t* b) {
    asm volatile(
        "mma.sync.aligned.m16n8k16.row.col.f32.bf16.bf16.f32 "
        "{%0,%1,%2,%3}, {%4,%5,%6,%7}, {%8,%9}, {%0,%1,%2,%3};"
        : "+f"(c[0]), "+f"(c[1]), "+f"(c[2]), "+f"(c[3])
        : "r"(a[0]), "r"(a[1]), "r"(a[2]), "r"(a[3]), "r"(b[0]), "r"(b[1]));
}

// Double-buffered cp.async HMMA 3-term split GEMM (dynamic smem, 80 KB).
constexpr int ROWB = 80;          // bytes per smem row
constexpr int ARRB = 128 * ROWB;  // 10240 bytes per array
constexpr int BUFB = 4 * ARRB;    // 40960 bytes per buffer
constexpr int HMMA_SMEM = 2 * BUFB;

template <bool FC_OUT, int KDIM>
__device__ __forceinline__ void hmma_tile(
        const __nv_bfloat16* __restrict__ Ahi, const __nv_bfloat16* __restrict__ Alo,
        const __nv_bfloat16* __restrict__ Bhi, const __nv_bfloat16* __restrict__ Blo,
        int m0, int n0, const float* __restrict__ bfc, float* __restrict__ out) {
    constexpr int NCH = KDIM / 32;
    extern __shared__ __align__(16) char smem[];
    const uint32_t sb = smem_u32(smem);

    const int tid = threadIdx.x;
    const int wid = tid >> 5;
    const int lane = tid & 31;
    const int wm = wid & 1;
    const int wn = wid >> 1;

    float acc[4][4][4];
#pragma unroll
    for (int i = 0; i < 4; i++)
#pragma unroll
        for (int j = 0; j < 4; j++)
#pragma unroll
            for (int q = 0; q < 4; q++) acc[i][j][q] = 0.f;

    const int a_row = wm * 64 + (lane & 15);
    const int a_cb = (lane >> 4) * 16;
    const int b_row = wn * 32 + (lane & 7);
    const int b_cb = ((lane >> 3) & 1) * 16;
    const int g_r0 = tid >> 2;
    const int g_c0 = (tid & 3) * 8;

#pragma unroll
    for (int i = 0; i < 2; i++) {
        const int row = g_r0 + i * 64;
        const size_t ga = (size_t)(m0 + row) * KDIM + g_c0;
        const size_t gb = (size_t)(n0 + row) * KDIM + g_c0;
        const uint32_t so = row * ROWB + g_c0 * 2;
        cpa16(sb + 0 * ARRB + so, Ahi + ga);
        cpa16(sb + 1 * ARRB + so, Alo + ga);
        cpa16(sb + 2 * ARRB + so, Bhi + gb);
        cpa16(sb + 3 * ARRB + so, Blo + gb);
    }
    CPA_COMMIT();

    for (int c = 0; c < NCH; c++) {
        const uint32_t cur = sb + (c & 1) * BUFB;
        CPA_WAIT0();
        __syncthreads();
        if (c < NCH - 1) {
            const uint32_t nxt = sb + ((c + 1) & 1) * BUFB;
            const int kg = (c + 1) * 32;
#pragma unroll
            for (int i = 0; i < 2; i++) {
                const int row = g_r0 + i * 64;
                const size_t ga = (size_t)(m0 + row) * KDIM + kg + g_c0;
                const size_t gb = (size_t)(n0 + row) * KDIM + kg + g_c0;
                const uint32_t so = row * ROWB + g_c0 * 2;
                cpa16(nxt + 0 * ARRB + so, Ahi + ga);
                cpa16(nxt + 1 * ARRB + so, Alo + ga);
                cpa16(nxt + 2 * ARRB + so, Bhi + gb);
                cpa16(nxt + 3 * ARRB + so, Blo + gb);
            }
            CPA_COMMIT();
        }

#pragma unroll
        for (int ks = 0; ks < 2; ks++) {
            const int kb = ks * 32;
            uint32_t ah[4][4], al[4][4], bh[4][2], bl[4][2];
#pragma unroll
            for (int mt = 0; mt < 4; mt++) {
                const uint32_t ro = (a_row + mt * 16) * ROWB + kb + a_cb;
                ldsm_x4(ah[mt][0], ah[mt][1], ah[mt][2], ah[mt][3],
                        cur + 0 * ARRB + ro);
                ldsm_x4(al[mt][0], al[mt][1], al[mt][2], al[mt][3],
                        cur + 1 * ARRB + ro);
            }
#pragma unroll
            for (int nt = 0; nt < 4; nt++) {
                const uint32_t ro = (b_row + nt * 8) * ROWB + kb + b_cb;
                ldsm_x2(bh[nt][0], bh[nt][1], cur + 2 * ARRB + ro);
                ldsm_x2(bl[nt][0], bl[nt][1], cur + 3 * ARRB + ro);
            }
#pragma unroll
            for (int mt = 0; mt < 4; mt++)
#pragma unroll
                for (int nt = 0; nt < 4; nt++) {
                    mma_bf16(acc[mt][nt], ah[mt], bh[nt]);
                    mma_bf16(acc[mt][nt], ah[mt], bl[nt]);
                    mma_bf16(acc[mt][nt], al[mt], bh[nt]);
                }
        }
    }

#pragma unroll
    for (int mt = 0; mt < 4; mt++) {
#pragma unroll
        for (int half = 0; half < 2; half++) {
            const int m = m0 + wm * 64 + mt * 16 + (lane >> 2) + half * 8;
            float* orow;
            if (FC_OUT) {
                const int tt = m >> 5, bb = m & 31;
                orow = out + ((size_t)(bb * NT + tt)) * NV;
            } else {
                orow = out + (size_t)m * NG;
            }
#pragma unroll
            for (int nt = 0; nt < 4; nt++) {
                const int n = n0 + wn * 32 + nt * 8 + (lane & 3) * 2;
                const float v0 = acc[mt][nt][half * 2 + 0];
                const float v1 = acc[mt][nt][half * 2 + 1];
                if (FC_OUT) {
                    if (n < NV) orow[n] = v0 + bfc[n];
                    if (n + 1 < NV) orow[n + 1] = v1 + bfc[n + 1];
                } else {
                    orow[n] = v0;
                    orow[n + 1] = v1;
                }
            }
        }
    }
}

__global__ void __launch_bounds__(256) k_fc_mma(const float* __restrict__ bfc,
                                                float* __restrict__ out) {
    hmma_tile<true, DH>(g_ahi, g_alo, g_bhi, g_blo,
                        blockIdx.y * 128, blockIdx.x * 128, bfc, out);
}

__global__ void __launch_bounds__(256) k_pgemm() {
    hmma_tile<false, DH>(g_ehi, g_elo, g_pbh, g_pbl,
                         blockIdx.y * 128, blockIdx.x * 128, nullptr, g_P);
}

// gx_emb[m][n] = emb_m . W_ih[n][:256]   (m = t*NB+b)
__global__ void __launch_bounds__(256) k_gxemb_mma() {
    hmma_tile<false, NE>(g_xhi, g_xlo, g_qbh, g_qbl,
                         blockIdx.y * 128, blockIdx.x * 128, nullptr, g_gxemb);
}

// ---------------------------------------------------------------------------
// K-loop: persistent, 512 thr x 128 blocks, TWO phases per step (r15 design).
//  A: combine h_{t-1} + energy partials
//  B: blocks 0-95: W_hh GEMM (kc=4, K=128); blocks 96-127: softmax + gih
// ---------------------------------------------------------------------------
struct SA {
    float dpart[8][64];
    float decs[64];
    float vsh[64];
    float ep[4][NS];
};
struct SB {
    float aw[NS];
};
struct SG {
    float As[32][64];
    float Bs[32][36];
};
union SmemU {
    SA a;
    SB b;
    SG g;
};

__device__ __forceinline__ void gate_gemm_hh(
        const float* __restrict__ W_hh, int wr0,
        const float* __restrict__ bsrc, int kc, SG& sg, int tid) {
    const int p0 = tid >> 4;
    const int bg = (tid & 15) * 2;
    unsigned long long acc0 = 0ull, acc1 = 0ull;

    const int arow = tid & 63;
    const int akq = (tid >> 6) * 4;
    const int bb = tid >> 4;
    const int bk2 = (tid & 15) * 2;
    const float* wrow = W_hh + (size_t)(wr0 + arow) * DH;

#pragma unroll
    for (int kt = 0; kt < 4; kt++) {
        const int kg0 = kc * 128 + kt * 32;
        float4 a4 = *reinterpret_cast<const float4*>(wrow + kg0 + akq);
        sg.As[akq + 0][arow] = a4.x;
        sg.As[akq + 1][arow] = a4.y;
        sg.As[akq + 2][arow] = a4.z;
        sg.As[akq + 3][arow] = a4.w;
        float2 b2 = __ldcg(reinterpret_cast<const float2*>(
            bsrc + bb * 512 + kg0 + bk2));
        sg.Bs[bk2 + 0][bb] = b2.x;
        sg.Bs[bk2 + 1][bb] = b2.y;
        __syncthreads();
#pragma unroll
        for (int kk = 0; kk < 32; kk++) {
            float2 av = *reinterpret_cast<const float2*>(&sg.As[kk][2 * p0]);
            unsigned long long a2 = pack2(av.x, av.y);
            float b0 = sg.Bs[kk][bg];
            float b1 = sg.Bs[kk][bg + 1];
            ffma2(acc0, a2, pack2(b0, b0));
            ffma2(acc1, a2, pack2(b1, b1));
        }
        __syncthreads();
    }
    const int r = wr0 + 2 * p0;
    float lo, hi;
    unpack2(acc0, lo, hi);
    *reinterpret_cast<float2*>(
        &g_gparth[((size_t)(kc * NB + bg)) * NG + r]) = make_float2(lo, hi);
    unpack2(acc1, lo, hi);
    *reinterpret_cast<float2*>(
        &g_gparth[((size_t)(kc * NB + bg + 1)) * NG + r]) = make_float2(lo, hi);
}

__global__ void __launch_bounds__(512) k_loop(
        const float* __restrict__ dec_init,
        const int* __restrict__ mask,
        const float* __restrict__ W_dec,
        const float* __restrict__ v,
        const float* __restrict__ W_hh,
        const float* __restrict__ b_ih,
        const float* __restrict__ b_hh,
        float* __restrict__ attn_out) {
    const int blk = blockIdx.x;
    const int tid = threadIdx.x;
    __shared__ SmemU sm;
    __shared__ __align__(16) float s_prev[DH];

    const int ab = blk >> 2;   // batch element (phase A)
    const int at = blk & 3;    // a-tile quadrant

    int par = (int)(ld_relaxed(&g_root) >> 31) ^ 1;

    for (int t = 0; t <= NT; t++) {
        // ---------------- Phase A: combine h_{t-1}, then energy
        if (t == 0) {
            s_prev[tid] = dec_init[ab * DH + tid];
        } else {
            const int i = tid;
            float gx[3], gh[3];
#pragma unroll
            for (int g = 0; g < 3; g++) {
                const int R = g * DH + i;
                gx[g] = __ldcg(&g_gxemb[((size_t)(t - 1) * NB + ab) * NG + R]) +
                        __ldcg(&g_gih[ab * NG + R]) + b_ih[R];
                float s2 = b_hh[R];
#pragma unroll
                for (int kc = 0; kc < NKC; kc++)
                    s2 += __ldcg(&g_gparth[((size_t)(kc * NB + ab)) * NG + R]);
                gh[g] = s2;
            }
            const float r = fast_sigmoid(gx[0] + gh[0]);
            const float z = fast_sigmoid(gx[1] + gh[1]);
            const float n = fast_tanh(gx[2] + r * gh[2]);
            const float hn = (1.0f - z) * n + z * s_prev[i];
            s_prev[i] = hn;
            if (at == 0) g_h[((size_t)(t - 1) * NB + ab) * DH + i] = hn;
        }
        if (t == NT) break;

        {
            const int a0 = at * 64;
            if (tid < 64) sm.a.vsh[tid] = v[a0 + tid];
            __syncthreads();

            {
                const int j = tid & 63;
                const int hq = tid >> 6;
                const float* W0 = W_dec + (size_t)(hq * 64) * NA + a0 + j;
                const float* pr = s_prev + hq * 64;
                float c[8];
#pragma unroll
                for (int u = 0; u < 8; u++) c[u] = 0.f;
#pragma unroll
                for (int h = 0; h < 64; h += 8) {
#pragma unroll
                    for (int u = 0; u < 8; u++)
                        c[u] += pr[h + u] * W0[(h + u) * NA];
                }
                float s0 = 0.f;
#pragma unroll
                for (int u = 0; u < 8; u++) s0 += c[u];
                sm.a.dpart[hq][j] = s0;
            }
            __syncthreads();
            if (tid < 64) {
                float s0 = 0.f;
#pragma unroll
                for (int q = 0; q < 8; q++) s0 += sm.a.dpart[q][tid];
                sm.a.decs[tid] = s0;
            }
            __syncthreads();

            {
                const int ah = tid >> 7;
                const int ss = tid & 127;
                const float* et =
                    g_encT + ((size_t)ab * NA + a0 + ah * 16) * NS + ss;
                const float* dv = sm.a.decs + ah * 16;
                const float* vv = sm.a.vsh + ah * 16;
                float c[4];
#pragma unroll
                for (int u = 0; u < 4; u++) c[u] = 0.f;
#pragma unroll
                for (int a = 0; a < 16; a += 4) {
#pragma unroll
                    for (int u = 0; u < 4; u++)
                        c[u] += tanh_hw(et[(a + u) * NS] + dv[a + u]) * vv[a + u];
                }
                sm.a.ep[ah][ss] = (c[0] + c[1]) + (c[2] + c[3]);
            }
            __syncthreads();
            if (tid < NS)
                g_epart[((size_t)ab * 4 + at) * NS + tid] =
                    (sm.a.ep[0][tid] + sm.a.ep[1][tid]) +
                    (sm.a.ep[2][tid] + sm.a.ep[3][tid]);
        }
        gbar(par);

        // ---------------- Phase B
        if (blk < 96) {
            const float* bsrc = (t == 0) ? dec_init
                                         : (g_h + (size_t)(t - 1) * NB * DH);
            gate_gemm_hh(W_hh, (blk >> 2) * 64, bsrc, blk & 3, sm.g, tid);
        } else {
            const int b = blk - 96;
            if (tid < 32) {
                float en[4];
#pragma unroll
                for (int j = 0; j < 4; j++) {
                    const int s = tid + j * 32;
                    const float* gp = g_epart + (size_t)(b * 4) * NS + s;
                    float x = (__ldcg(gp) + __ldcg(gp + NS)) +
                              (__ldcg(gp + 2 * NS) + __ldcg(gp + 3 * NS));
                    if (mask[b * NS + s] == 0) x = -1e9f;
                    en[j] = x;
                }
                float mx = fmaxf(fmaxf(en[0], en[1]), fmaxf(en[2], en[3]));
#pragma unroll
                for (int off = 16; off > 0; off >>= 1)
                    mx = fmaxf(mx, __shfl_xor_sync(0xffffffffu, mx, off));
                float sum = 0.f;
#pragma unroll
                for (int j = 0; j < 4; j++) {
                    en[j] = __expf(en[j] - mx);
                    sum += en[j];
                }
#pragma unroll
                for (int off = 16; off > 0; off >>= 1)
                    sum += __shfl_xor_sync(0xffffffffu, sum, off);
                const float inv = 1.0f / sum;
#pragma unroll
                for (int j = 0; j < 4; j++) {
                    const float w = en[j] * inv;
                    sm.b.aw[tid + j * 32] = w;
                    attn_out[((size_t)(b * NT + t)) * NS + tid + j * 32] = w;
                }
            }
            __syncthreads();
            if (tid < 384) {
                const int R = tid * 4;
                const float* pb = g_P + ((size_t)b * NS) * NG + R;
                float4 c[4];
#pragma unroll
                for (int q = 0; q < 4; q++) c[q] = make_float4(0.f, 0.f, 0.f, 0.f);
#pragma unroll 2
                for (int s = 0; s < NS; s += 4) {
#pragma unroll
                    for (int q = 0; q < 4; q++) {
                        float4 vv = __ldcg(reinterpret_cast<const float4*>(
                            pb + (size_t)(s + q) * NG));
                        const float w = sm.b.aw[s + q];
                        c[q].x += w * vv.x;
                        c[q].y += w * vv.y;
                        c[q].z += w * vv.z;
                        c[q].w += w * vv.w;
                    }
                }
                float4 o;
                o.x = (c[0].x + c[1].x) + (c[2].x + c[3].x);
                o.y = (c[0].y + c[1].y) + (c[2].y + c[3].y);
                o.z = (c[0].z + c[1].z) + (c[2].z + c[3].z);
                o.w = (c[0].w + c[1].w) + (c[2].w + c[3].w);
                *reinterpret_cast<float4*>(&g_gih[b * NG + R]) = o;
            }
        }
        gbar(par);
    }
}

// ---------------------------------------------------------------------------
// Launch
// ---------------------------------------------------------------------------
extern "C" void kernel_launch(void* const* d_in, const int* in_sizes, int n_in,
                              void* d_out, int out_size) {
    const int* y = (const int*)d_in[0];
    const float* enc = (const float*)d_in[1];
    const float* dec_init = (const float*)d_in[2];
    const int* mask = (const int*)d_in[3];
    const float* emb = (const float*)d_in[4];
    const float* W_enc = (const float*)d_in[5];
    const float* W_dec = (const float*)d_in[6];
    const float* v = (const float*)d_in[7];
    const float* W_ih = (const float*)d_in[8];
    const float* W_hh = (const float*)d_in[9];
    const float* b_ih = (const float*)d_in[10];
    const float* b_hh = (const float*)d_in[11];
    const float* W_fc = (const float*)d_in[12];
    const float* b_fc = (const float*)d_in[13];

    float* out = (float*)d_out;
    float* attn_out = out + (size_t)NB * NT * NV;

    cudaFuncSetAttribute(k_fc_mma, cudaFuncAttributeMaxDynamicSharedMemorySize,
                         HMMA_SMEM);
    cudaFuncSetAttribute(k_pgemm, cudaFuncAttributeMaxDynamicSharedMemorySize,
                         HMMA_SMEM);
    cudaFuncSetAttribute(k_gxemb_mma,
                         cudaFuncAttributeMaxDynamicSharedMemorySize, HMMA_SMEM);

    k_encproj<<<NB * NS, 256>>>(enc, W_enc);
    k_gather_emb<<<(NM * NE) / (256 * 4), 256>>>(y, emb);
    k_split_wq<<<(NG * NE) / (256 * 4), 256>>>(W_ih);
    k_split_w<<<dim3(NVP / 32, DH / 32), 256>>>(W_fc);
    k_split_enc<<<(NB * NS * EH) / (256 * 4), 256>>>(enc);
    k_split_wp<<<(NG * EH) / (256 * 4), 256>>>(W_ih);
    k_gxemb_mma<<<dim3(NG / 128, NM / 128), 256, HMMA_SMEM>>>();
    k_pgemm<<<dim3(NG / 128, (NB * NS) / 128), 256, HMMA_SMEM>>>();
    k_loop<<<NBLK, 512>>>(dec_init, mask, W_dec, v, W_hh, b_ih, b_hh, attn_out);
    k_split_h<<<(NM * DH) / (256 * 4), 256>>>();
    k_fc_mma<<<dim3(NVP / 128, NM / 128), 256, HMMA_SMEM>>>(b_fc, out);
}